// round 5
// baseline (speedup 1.0000x reference)
#include <cuda_runtime.h>
#include <cstdint>

#define N_  4
#define C_  128
#define H_  128
#define W_  128
#define OC  8
#define OH  256
#define OW  256
#define HW  (H_*W_)

typedef unsigned long long ull;

// Per-channel-group partial conv outputs: [cg][n][o][h][w]
__device__ float g_part[4][N_*OC*H_*W_];

// ---- f32x2 helpers ----
__device__ __forceinline__ ull pack2(float lo, float hi) {
    ull r;
    asm("mov.b64 %0, {%1, %2};" : "=l"(r) : "f"(lo), "f"(hi));
    return r;
}
__device__ __forceinline__ void unpack2(ull v, float& lo, float& hi) {
    asm("mov.b64 {%0, %1}, %2;" : "=f"(lo), "=f"(hi) : "l"(v));
}
__device__ __forceinline__ ull fma2(ull a, ull b, ull c) {
    ull d;
    asm("fma.rn.f32x2 %0, %1, %2, %3;" : "=l"(d) : "l"(a), "l"(b), "l"(c));
    return d;
}

// ---------------------------------------------------------------------------
// Kernel 1: 3x3 SAME conv, 32-channel partial per block.
// 256 threads, 32x32 pixel tile. f32x2 lanes = output-channel pair.
// Thread = 4x2 pixel patch x 4 outputs (2 o-pairs) -> 16 ull accumulators.
// Weights prepacked {w_even,w_odd} in smem; one LDS.128 per tap fetches
// both o-pairs. Grid (4,4,16), bz = n*4+cg.
// ---------------------------------------------------------------------------
__global__ __launch_bounds__(256, 2) void conv_part_kernel(
    const float* __restrict__ x,
    const float* __restrict__ wt,    // [o][c][3][3]
    const float* __restrict__ bs)    // [o]
{
    __shared__ float xs[8][34*34];   // 8 channels, 34x34 halo tile
    __shared__ ull ws2[8][9][4];     // [cc][tap][opair] = {w_{2p}, w_{2p+1}}

    const int tid = threadIdx.x;
    const int n  = blockIdx.z >> 2;
    const int cg = blockIdx.z & 3;
    const int h0 = blockIdx.y * 32;
    const int w0 = blockIdx.x * 32;

    const int osel = tid & 1;        // outputs osel*4 .. osel*4+3
    const int g    = tid >> 1;       // pixel group 0..127
    const int gx   = g & 15;         // cols w0+2gx, w0+2gx+1
    const int gy   = g >> 4;         // rows h0+4gy .. h0+4gy+3

    // acc[op][r*2+pc] : op in {0,1} (o-pairs), r row 0..3, pc col 0..1
    ull acc[2][8];
    if (cg == 0) {
#pragma unroll
        for (int op = 0; op < 2; op++) {
            float be = __ldg(&bs[osel*4 + op*2    ]);
            float bo = __ldg(&bs[osel*4 + op*2 + 1]);
            ull bb = pack2(be, bo);
#pragma unroll
            for (int p = 0; p < 8; p++) acc[op][p] = bb;
        }
    } else {
#pragma unroll
        for (int op = 0; op < 2; op++)
#pragma unroll
            for (int p = 0; p < 8; p++) acc[op][p] = 0ull;
    }

    const float* xn = x + ((size_t)n*C_ + cg*32) * HW;

    for (int ch = 0; ch < 4; ch++) {
        const int c0 = ch * 8;
        __syncthreads();
        // Stage weights prepacked as o-pairs
        for (int i = tid; i < 8*9*4; i += 256) {
            int pr  = i & 3;
            int tap = (i >> 2) % 9;
            int cc  = i / 36;
            int c   = cg*32 + c0 + cc;
            float we = wt[((size_t)(2*pr    )*C_ + c)*9 + tap];
            float wo = wt[((size_t)(2*pr + 1)*C_ + c)*9 + tap];
            ws2[cc][tap][pr] = pack2(we, wo);
        }
        // Stage 8 channels of 34x34 halo tile (zero padded)
#pragma unroll
        for (int cc = 0; cc < 8; cc++) {
            const float* xc = xn + (c0+cc)*HW;
            for (int i = tid; i < 34*34; i += 256) {
                int ly = i / 34;
                int lx = i - ly*34;
                int gyy = h0 - 1 + ly;
                int gxx = w0 - 1 + lx;
                float v = 0.f;
                if ((unsigned)gyy < H_ && (unsigned)gxx < W_)
                    v = xc[gyy*W_ + gxx];
                xs[cc][i] = v;
            }
        }
        __syncthreads();

#pragma unroll
        for (int cc = 0; cc < 8; cc++) {
            // halo cols 2gx..2gx+3, rows 4gy..4gy+5
            const float* xb = &xs[cc][(4*gy)*34 + 2*gx];
            float2 va[6], vb[6];
#pragma unroll
            for (int s = 0; s < 6; s++) {
                va[s] = *reinterpret_cast<const float2*>(xb + s*34);
                vb[s] = *reinterpret_cast<const float2*>(xb + s*34 + 2);
            }
#pragma unroll
            for (int kx = 0; kx < 3; kx++) {
                // dup columns kx and kx+1 into lanes
                ull d0[6], d1[6];
#pragma unroll
                for (int s = 0; s < 6; s++) {
                    float c0v = (kx == 0) ? va[s].x : (kx == 1) ? va[s].y : vb[s].x;
                    float c1v = (kx == 0) ? va[s].y : (kx == 1) ? vb[s].x : vb[s].y;
                    d0[s] = pack2(c0v, c0v);
                    d1[s] = pack2(c1v, c1v);
                }
#pragma unroll
                for (int ky = 0; ky < 3; ky++) {
                    // one LDS.128: both o-pairs for this tap
                    ulonglong2 w2 = *reinterpret_cast<const ulonglong2*>(&ws2[cc][ky*3 + kx][2*osel]);
#pragma unroll
                    for (int r = 0; r < 4; r++) {
                        acc[0][r*2  ] = fma2(d0[r+ky], w2.x, acc[0][r*2  ]);
                        acc[0][r*2+1] = fma2(d1[r+ky], w2.x, acc[0][r*2+1]);
                        acc[1][r*2  ] = fma2(d0[r+ky], w2.y, acc[1][r*2  ]);
                        acc[1][r*2+1] = fma2(d1[r+ky], w2.y, acc[1][r*2+1]);
                    }
                }
            }
        }
    }

    float* gp = g_part[cg];
#pragma unroll
    for (int op = 0; op < 2; op++) {
        int oe = osel*4 + op*2;
#pragma unroll
        for (int r = 0; r < 4; r++) {
            float e0, o0, e1, o1;
            unpack2(acc[op][r*2  ], e0, o0);
            unpack2(acc[op][r*2+1], e1, o1);
            int h = h0 + 4*gy + r;
            int w = w0 + 2*gx;
            size_t be = (((size_t)n*OC + oe    )*H_ + h)*W_ + w;
            size_t bo = (((size_t)n*OC + oe + 1)*H_ + h)*W_ + w;
            *reinterpret_cast<float2*>(&gp[be]) = make_float2(e0, e1);
            *reinterpret_cast<float2*>(&gp[bo]) = make_float2(o0, o1);
        }
    }
}

// ---------------------------------------------------------------------------
// Kernel 2: bilinear sampling + pixel shuffle.
// One block per (n, h, kh): 256 threads, tid = w*2 + kw (one point/thread).
// Channel loop x4 unrolled: 16 independent LDGs in flight per thread.
// ---------------------------------------------------------------------------
__global__ __launch_bounds__(256) void sample_kernel(
    const float* __restrict__ x,
    float* __restrict__ out)
{
    __shared__ float soff[4][W_];   // [kw*2+d][w] for this kh

    const int b  = blockIdx.x;
    const int kh = b & 1;
    const int h  = (b >> 1) & (H_-1);
    const int n  = b >> 8;
    const int tid = threadIdx.x;

    for (int i = tid; i < 4*W_; i += 256) {
        int j  = i >> 7;
        int ww = i & (W_-1);
        int o  = (kh*2 + (j >> 1))*2 + (j & 1);
        size_t idx = (((size_t)n*OC + o)*H_ + h)*W_ + ww;
        soff[j][ww] = g_part[0][idx] + g_part[1][idx] + g_part[2][idx] + g_part[3][idx];
    }
    __syncthreads();

    const int kw = tid & 1;
    const int w  = tid >> 1;

    float sy = (float)h + soff[kw*2    ][w];
    float sx = (float)w + soff[kw*2 + 1][w];
    float y0f = floorf(sy), x0f = floorf(sx);
    int   y0 = (int)y0f,   x0 = (int)x0f;
    float fy = sy - y0f,   fx = sx - x0f;

    float cw[4];
    cw[0] = (1.f - fy) * (1.f - fx);
    cw[1] = (1.f - fy) * fx;
    cw[2] = fy * (1.f - fx);
    cw[3] = fy * fx;
    const float* p[4];
    const float* xbase = x + (size_t)n*C_*HW;
#pragma unroll
    for (int k = 0; k < 4; k++) {
        int yi = y0 + (k >> 1);
        int xi = x0 + (k & 1);
        bool valid = ((unsigned)yi < H_) && ((unsigned)xi < W_);
        int yc = min(max(yi, 0), H_-1);
        int xc = min(max(xi, 0), W_-1);
        p[k] = xbase + yc*W_ + xc;
        if (!valid) cw[k] = 0.f;
    }

    float* op = out + ((size_t)n*C_)*OH*OW + (size_t)(2*h + kh)*OW + (2*w + kw);

    for (int c = 0; c < C_; c += 4) {
        float v[16];
#pragma unroll
        for (int u = 0; u < 4; u++)
#pragma unroll
            for (int k = 0; k < 4; k++)
                v[u*4+k] = __ldg(p[k] + (size_t)u*HW);

#pragma unroll
        for (int u = 0; u < 4; u++) {
            float r = v[u*4+0]*cw[0];
            r = fmaf(v[u*4+1], cw[1], r);
            r = fmaf(v[u*4+2], cw[2], r);
            r = fmaf(v[u*4+3], cw[3], r);
            op[(size_t)u*OH*OW] = r;
        }
#pragma unroll
        for (int k = 0; k < 4; k++) p[k] += (size_t)4*HW;
        op += (size_t)4*OH*OW;
    }
}

// ---------------------------------------------------------------------------
extern "C" void kernel_launch(void* const* d_in, const int* in_sizes, int n_in,
                              void* d_out, int out_size)
{
    const float* x  = (const float*)d_in[0];
    const float* wt = (const float*)d_in[1];
    const float* bs = (const float*)d_in[2];
    float* out = (float*)d_out;

    conv_part_kernel<<<dim3(4, 4, 16), 256>>>(x, wt, bs);
    sample_kernel<<<N_*H_*2, 256>>>(x, out);
}